// round 14
// baseline (speedup 1.0000x reference)
#include <cuda_runtime.h>
#include <cuda_fp16.h>
#include <cstdint>
#include <math.h>

#define SQ 2048
#define NH 16
#define DM 1024
#define DH 64

__device__ __half g_q[NH * SQ * DH];      // pre-scaled by log2e/8, fp16
__device__ __half g_k[NH * SQ * DH];      // fp16
__device__ __half g_vt[NH * DH * SQ];     // V^T: [h][e][s], fp16
__device__ float  g_z[NH * SQ * DH];
__device__ float  g_wt[3][NH * DH * DM];  // W^T, tf32-rounded
__device__ float  g_wot[NH * DM * DH];    // W_O^T, tf32-rounded
__device__ float2 g_rope[SQ * 32];        // (sin, cos) per (pos, j)

__device__ __forceinline__ uint32_t smem_u32(const void* p) {
    uint32_t a;
    asm("{ .reg .u64 t; cvta.to.shared.u64 t, %1; cvt.u32.u64 %0, t; }" : "=r"(a) : "l"(p));
    return a;
}
#define SWZ128(x) ((x) ^ (((x) >> 3) & 0x70))

__device__ __forceinline__ float to_tf32(float x) {
    float y;
    asm("cvt.rna.tf32.f32 %0, %1;" : "=f"(y) : "f"(x));
    return y;
}
__device__ __forceinline__ float ex2(float x) {
    float y;
    asm("ex2.approx.ftz.f32 %0, %1;" : "=f"(y) : "f"(x));
    return y;
}
__device__ __forceinline__ uint32_t packh2(float lo, float hi) {
    uint32_t r;
    asm("cvt.rn.f16x2.f32 %0, %1, %2;" : "=r"(r) : "f"(hi), "f"(lo));
    return r;
}
__device__ __forceinline__ uint32_t h2ex2(uint32_t x) {
    uint32_t y;
    asm("ex2.approx.f16x2 %0, %1;" : "=r"(y) : "r"(x));
    return y;
}
__device__ __forceinline__ void ldsm_x4(uint32_t& r0, uint32_t& r1, uint32_t& r2,
                                        uint32_t& r3, uint32_t addr) {
    asm volatile("ldmatrix.sync.aligned.m8n8.x4.shared.b16 {%0,%1,%2,%3}, [%4];"
                 : "=r"(r0), "=r"(r1), "=r"(r2), "=r"(r3) : "r"(addr));
}
__device__ __forceinline__ void mma_tf32(float* c, const uint32_t* a,
                                         uint32_t b0, uint32_t b1) {
    asm volatile(
        "mma.sync.aligned.m16n8k8.row.col.f32.tf32.tf32.f32 "
        "{%0,%1,%2,%3}, {%4,%5,%6,%7}, {%8,%9}, {%0,%1,%2,%3};"
        : "+f"(c[0]), "+f"(c[1]), "+f"(c[2]), "+f"(c[3])
        : "r"(a[0]), "r"(a[1]), "r"(a[2]), "r"(a[3]), "r"(b0), "r"(b1));
}
__device__ __forceinline__ void mma_f16(float* c, const uint32_t* a,
                                        uint32_t b0, uint32_t b1) {
    asm volatile(
        "mma.sync.aligned.m16n8k16.row.col.f32.f16.f16.f32 "
        "{%0,%1,%2,%3}, {%4,%5,%6,%7}, {%8,%9}, {%0,%1,%2,%3};"
        : "+f"(c[0]), "+f"(c[1]), "+f"(c[2]), "+f"(c[3])
        : "r"(a[0]), "r"(a[1]), "r"(a[2]), "r"(a[3]), "r"(b0), "r"(b1));
}
#define CP_ASYNC16(dst, src) \
    asm volatile("cp.async.cg.shared.global [%0], [%1], 16;" :: "r"(dst), "l"(src))
#define CP_COMMIT() asm volatile("cp.async.commit_group;" ::: "memory")
#define CP_WAIT(n)  asm volatile("cp.async.wait_group %0;" :: "n"(n) : "memory")

// ---------------- RoPE table ----------------------------------------------------
__global__ void rope_tab_kernel()
{
    const int idx = blockIdx.x * 256 + threadIdx.x;
    const int pos = idx >> 5, j = idx & 31;
    const float L2B = 0.41524101186092029f;           // log2(10000)/32
    float invf = exp2f(-(float)j * L2B);
    float sn, cs;
    sincosf((float)pos * invf, &sn, &cs);
    g_rope[idx] = make_float2(sn, cs);
}

// ---------------- W transpose (+tf32 round) -----------------------------------
__global__ void transpose_w_kernel(const float* __restrict__ WQ, const float* __restrict__ WK,
                                   const float* __restrict__ WV, const float* __restrict__ WO)
{
    __shared__ float t[32][33];
    const int m = blockIdx.y >> 4, h = blockIdx.y & 15;
    const float* src; float* dst; int R, C;
    if (m == 0)      { src = WQ + (size_t)h*DM*DH; dst = g_wt[0] + (size_t)h*DH*DM; R = DM; C = DH; }
    else if (m == 1) { src = WK + (size_t)h*DM*DH; dst = g_wt[1] + (size_t)h*DH*DM; R = DM; C = DH; }
    else if (m == 2) { src = WV + (size_t)h*DM*DH; dst = g_wt[2] + (size_t)h*DH*DM; R = DM; C = DH; }
    else             { src = WO + (size_t)h*DH*DM; dst = g_wot   + (size_t)h*DM*DH; R = DH; C = DM; }
    const int nrt = R / 32, rt = blockIdx.x % nrt, ct = blockIdx.x / nrt;
    const int x = ct * 32 + threadIdx.x;
    #pragma unroll
    for (int j = 0; j < 4; j++)
        t[threadIdx.y + j*8][threadIdx.x] =
            to_tf32(src[(size_t)(rt*32 + threadIdx.y + j*8) * C + x]);
    __syncthreads();
    const int xo = rt * 32 + threadIdx.x;
    #pragma unroll
    for (int j = 0; j < 4; j++)
        dst[(size_t)(ct*32 + threadIdx.y + j*8) * R + xo] = t[threadIdx.x][threadIdx.y + j*8];
}

// ---------------- Projection via HMMA tf32, 2-stage cp.async, 2 CTAs/SM --------
// dyn smem: A 2x16KB @0, B 2x8KB @32768 = 49152B
__global__ __launch_bounds__(256, 2) void proj_mma_kernel(
    const float* __restrict__ xq, const float* __restrict__ xk, const float* __restrict__ xv,
    const float* __restrict__ bQ, const float* __restrict__ bK, const float* __restrict__ bV)
{
    extern __shared__ uint8_t dsm[];
    const uint32_t sA = smem_u32(dsm);
    const uint32_t sB = sA + 32768;

    const int tid = threadIdx.x, w = tid >> 5, lane = tid & 31;
    const int h = blockIdx.y, which = blockIdx.z;
    const int s0 = blockIdx.x * 128;

    const float* X    = (which == 0) ? xq : (which == 1) ? xk : xv;
    const float* bias = (which == 0) ? bQ : (which == 1) ? bK : bV;
    const float* WT   = g_wt[which] + (size_t)h * DH * DM;

    const int mw = w * 16;
    const int g  = lane >> 3, l7 = lane & 7;

    auto prefetch = [&](int c) {
        const int k0 = c * 32;
        const uint32_t ab = sA + (uint32_t)((c & 1) * 16384);
        const uint32_t bb = sB + (uint32_t)((c & 1) * 8192);
        #pragma unroll
        for (int i = 0; i < 4; i++) {
            int idx = tid + i * 256, r = idx >> 3, q = idx & 7;
            CP_ASYNC16(ab + SWZ128((uint32_t)(r*128 + q*16)),
                       &X[(((size_t)(s0 + r)) * NH + h) * DM + k0 + q*4]);
        }
        #pragma unroll
        for (int i = 0; i < 2; i++) {
            int idx = tid + i * 256, n = idx >> 3, q = idx & 7;
            CP_ASYNC16(bb + SWZ128((uint32_t)(n*128 + q*16)),
                       &WT[(size_t)n * DM + k0 + q*4]);
        }
    };

    float acc[8][4] = {};

    prefetch(0); CP_COMMIT();
    prefetch(1); CP_COMMIT();

    #pragma unroll 1
    for (int c = 0; c < 32; c++) {
        CP_WAIT(1);
        __syncthreads();

        const uint32_t sbA = sA + (uint32_t)((c & 1) * 16384);
        const uint32_t sbB = sB + (uint32_t)((c & 1) * 8192);
        #pragma unroll
        for (int kk = 0; kk < 4; kk++) {
            const int kb = kk * 32;
            uint32_t a[4];
            {
                int row = mw + ((g & 1) << 3) + l7;
                int byo = kb + ((g >> 1) << 4);
                ldsm_x4(a[0], a[1], a[2], a[3], sbA + SWZ128((uint32_t)(row*128 + byo)));
            }
            uint32_t b[16];
            #pragma unroll
            for (int nb = 0; nb < 4; nb++) {
                int row = nb * 16 + ((g >> 1) << 3) + l7;
                int byo = kb + ((g & 1) << 4);
                ldsm_x4(b[nb*4+0], b[nb*4+1], b[nb*4+2], b[nb*4+3],
                        sbB + SWZ128((uint32_t)(row*128 + byo)));
            }
            #pragma unroll
            for (int ni = 0; ni < 8; ni++)
                mma_tf32(acc[ni], a, b[(ni >> 1)*4 + (ni & 1)*2],
                                     b[(ni >> 1)*4 + (ni & 1)*2 + 1]);
        }

        __syncthreads();     // all done reading buffer (c&1)
        if (c + 2 < 32) { prefetch(c + 2); }
        CP_COMMIT();
    }

    const int r0 = mw + (lane >> 2);
    const int ec = (lane & 3) * 2;

    #pragma unroll
    for (int ni = 0; ni < 8; ni++) {
        float bv0 = bias[h * DH + ni*8 + ec];
        float bv1 = bias[h * DH + ni*8 + ec + 1];
        acc[ni][0] += bv0; acc[ni][1] += bv1;
        acc[ni][2] += bv0; acc[ni][3] += bv1;
    }

    if (which < 2) {
        #pragma unroll
        for (int ni = 0; ni < 4; ni++) {
            #pragma unroll
            for (int cc = 0; cc < 2; cc++) {
                int j = ni*8 + ec + cc;
                #pragma unroll
                for (int rr = 0; rr < 2; rr++) {
                    float2 sc = g_rope[(s0 + r0 + rr*8) * 32 + j];
                    int ci = rr*2 + cc;
                    float x = acc[ni][ci], y = acc[ni+4][ci];
                    acc[ni][ci]   = x*sc.y - y*sc.x;
                    acc[ni+4][ci] = y*sc.y + x*sc.x;
                }
            }
        }
    }

    if (which == 2) {
        #pragma unroll
        for (int ni = 0; ni < 8; ni++) {
            int e = ni*8 + ec;
            int sg0 = s0 + r0, sg1 = sg0 + 8;
            g_vt[((size_t)h*DH + e    ) * SQ + sg0] = __float2half_rn(acc[ni][0]);
            g_vt[((size_t)h*DH + e + 1) * SQ + sg0] = __float2half_rn(acc[ni][1]);
            g_vt[((size_t)h*DH + e    ) * SQ + sg1] = __float2half_rn(acc[ni][2]);
            g_vt[((size_t)h*DH + e + 1) * SQ + sg1] = __float2half_rn(acc[ni][3]);
        }
    } else {
        const float osc = (which == 0) ? 0.18033688011112042f : 1.0f;   // log2e/8
        __half* out = (which == 0) ? g_q : g_k;
        #pragma unroll
        for (int ni = 0; ni < 8; ni++) {
            int e = ni*8 + ec;
            *(uint32_t*)&out[((size_t)h*SQ + s0 + r0    ) * DH + e] =
                packh2(acc[ni][0]*osc, acc[ni][1]*osc);
            *(uint32_t*)&out[((size_t)h*SQ + s0 + r0 + 8) * DH + e] =
                packh2(acc[ni][2]*osc, acc[ni][3]*osc);
        }
    }
}

// ---------------- Attention: fp16 HMMA; f16x2 exp; row-sum via ones-mma ---------
// dynamic smem: Q @0 (8KB), K @8192 (2x8KB), V @24576 (2x8KB) = 40KB
__global__ __launch_bounds__(128, 2) void attn_mma_kernel()
{
    extern __shared__ uint8_t dsm[];
    const uint32_t sQ = smem_u32(dsm);
    const uint32_t sK = sQ + 8192;
    const uint32_t sV = sQ + 24576;

    const int tid = threadIdx.x, w = tid >> 5, lane = tid & 31;
    const int h = blockIdx.y;
    const int g = lane >> 3, l7 = lane & 7;
    const int mw = w * 16;
    const int r_loc = lane >> 2, ec = (lane & 3) * 2;
    const uint32_t H2ONE = 0x3C003C00u;

    auto load_kv = [&](int kt) {
        const int kk0 = kt * 64;
        const uint32_t boff = (uint32_t)((kt & 1) * 8192);
        #pragma unroll
        for (int i = 0; i < 4; i++) {
            int idx = tid + i * 128, r = idx >> 3, q = idx & 7;
            uint32_t off = boff + SWZ128((uint32_t)(r*128 + q*16));
            CP_ASYNC16(sK + off, &g_k [((size_t)h*SQ + kk0 + r) * DH + q*8]);
            CP_ASYNC16(sV + off, &g_vt[((size_t)h*DH + r) * SQ + kk0 + q*8]);
        }
    };

    for (int rep = 0; rep < 2; rep++) {
        const int qb = rep ? (31 - (int)blockIdx.x) : (int)blockIdx.x;
        const int q0 = qb * 64;

        __syncthreads();
        #pragma unroll
        for (int i = 0; i < 4; i++) {
            int idx = tid + i * 128, r = idx >> 3, q = idx & 7;
            CP_ASYNC16(sQ + SWZ128((uint32_t)(r*128 + q*16)),
                       &g_q[((size_t)h*SQ + q0 + r) * DH + q*8]);
        }
        CP_COMMIT();
        load_kv(0);
        CP_COMMIT();
        CP_WAIT(1);
        __syncthreads();

        uint32_t qa[4][4];
        #pragma unroll
        for (int kc = 0; kc < 4; kc++) {
            int row = mw + ((g & 1) << 3) + l7;
            int byo = kc*32 + ((g >> 1) << 4);
            ldsm_x4(qa[kc][0], qa[kc][1], qa[kc][2], qa[kc][3],
                    sQ + SWZ128((uint32_t)(row*128 + byo)));
        }

        float m0 = -1e30f, m1 = -1e30f, l0 = 0.f, l1 = 0.f;
        float oa[8][4] = {};

        for (int kt = 0; kt <= qb; kt++) {
            const uint32_t kb_off = (uint32_t)((kt & 1) * 8192);
            CP_WAIT(0);
            __syncthreads();
            if (kt < qb) load_kv(kt + 1);
            CP_COMMIT();

            float sacc[8][4] = {};
            #pragma unroll
            for (int kc = 0; kc < 4; kc++) {
                uint32_t b[16];
                #pragma unroll
                for (int nb = 0; nb < 4; nb++) {
                    int row = nb*16 + ((g >> 1) << 3) + l7;
                    int byo = kc*32 + ((g & 1) << 4);
                    ldsm_x4(b[nb*4+0], b[nb*4+1], b[nb*4+2], b[nb*4+3],
                            sK + kb_off + SWZ128((uint32_t)(row*128 + byo)));
                }
                #pragma unroll
                for (int ni = 0; ni < 8; ni++)
                    mma_f16(sacc[ni], qa[kc], b[(ni>>1)*4 + (ni&1)*2],
                                              b[(ni>>1)*4 + (ni&1)*2 + 1]);
            }

            const bool diag = (kt == qb);
            if (diag) {
                #pragma unroll
                for (int ni = 0; ni < 8; ni++) {
                    int col = ni*8 + ec;
                    int row0 = mw + r_loc, row1 = row0 + 8;
                    if (col     > row0) sacc[ni][0] = -1e30f;
                    if (col + 1 > row0) sacc[ni][1] = -1e30f;
                    if (col     > row1) sacc[ni][2] = -1e30f;
                    if (col + 1 > row1) sacc[ni][3] = -1e30f;
                }
            }

            float rx0 = -1e30f, rx1 = -1e30f;
            #pragma unroll
            for (int ni = 0; ni < 8; ni++) {
                rx0 = fmaxf(rx0, fmaxf(sacc[ni][0], sacc[ni][1]));
                rx1 = fmaxf(rx1, fmaxf(sacc[ni][2], sacc[ni][3]));
            }
            rx0 = fmaxf(rx0, __shfl_xor_sync(0xffffffffu, rx0, 1));
            rx0 = fmaxf(rx0, __shfl_xor_sync(0xffffffffu, rx0, 2));
            rx1 = fmaxf(rx1, __shfl_xor_sync(0xffffffffu, rx1, 1));
            rx1 = fmaxf(rx1, __shfl_xor_sync(0xffffffffu, rx1, 2));
            float mn0 = fmaxf(m0, rx0), mn1 = fmaxf(m1, rx1);
            float c0 = ex2(m0 - mn0), c1 = ex2(m1 - mn1);

            uint32_t prow0[8], prow1[8];
            #pragma unroll
            for (int ni = 0; ni < 8; ni++) {
                prow0[ni] = h2ex2(packh2(sacc[ni][0] - mn0, sacc[ni][1] - mn0));
                prow1[ni] = h2ex2(packh2(sacc[ni][2] - mn1, sacc[ni][3] - mn1));
            }

            m0 = mn0; m1 = mn1;
            #pragma unroll
            for (int ni = 0; ni < 8; ni++) {
                oa[ni][0] *= c0; oa[ni][1] *= c0;
                oa[ni][2] *= c1; oa[ni][3] *= c1;
            }

            float lacc[4] = {};
            #pragma unroll
            for (int ks = 0; ks < 4; ks++) {
                uint32_t a[4];
                a[0] = prow0[2*ks];
                a[1] = prow1[2*ks];
                a[2] = prow0[2*ks+1];
                a[3] = prow1[2*ks+1];

                mma_f16(lacc, a, H2ONE, H2ONE);

                uint32_t b[16];
                #pragma unroll
                for (int nb = 0; nb < 4; nb++) {
                    int rowb = nb*16 + ((g >> 1) << 3) + l7;
                    int byob = ks*32 + ((g & 1) << 4);
                    ldsm_x4(b[nb*4+0], b[nb*4+1], b[nb*4+2], b[nb*4+3],
                            sV + kb_off + SWZ128((uint32_t)(rowb*128 + byob)));
                }
                #pragma unroll
                for (int ni = 0; ni < 8; ni++)
                    mma_f16(oa[ni], a, b[(ni>>1)*4 + (ni&1)*2],
                                       b[(ni>>1)*4 + (ni&1)*2 + 1]);
            }
            l0 = l0 * c0 + lacc[0];
            l1 = l1 * c1 + lacc[2];
        }

        float inv0 = 1.f / l0, inv1 = 1.f / l1;
        int row0 = q0 + mw + r_loc;
        #pragma unroll
        for (int ni = 0; ni < 8; ni++) {
            int e = ni*8 + ec;
            *(float2*)&g_z[((size_t)h*SQ + row0    ) * DH + e] =
                make_float2(to_tf32(oa[ni][0]*inv0), to_tf32(oa[ni][1]*inv0));
            *(float2*)&g_z[((size_t)h*SQ + row0 + 8) * DH + e] =
                make_float2(to_tf32(oa[ni][2]*inv1), to_tf32(oa[ni][3]*inv1));
        }
    }
}

// ---------------- Output projection, persistent, d-tile 64, 2 CTAs/SM -----------
// dyn smem: Z @0 (32KB), W @32768 (3x16KB) = 80KB
__global__ __launch_bounds__(256, 2) void outproj_mma_kernel(
    const float* __restrict__ bO, float* __restrict__ out)
{
    extern __shared__ uint8_t dsm[];
    const uint32_t sZ = smem_u32(dsm);
    const uint32_t sW = sZ + 32768;

    const int tid = threadIdx.x, w = tid >> 5, lane = tid & 31;
    const int s0 = blockIdx.x * 128, h = blockIdx.y;
    const float* WOT = g_wot + (size_t)h * DM * DH;

    const int mw = w * 16;
    const int g  = lane >> 3, l7 = lane & 7;

    auto prefetch_w = [&](int d) {
        const int d0 = d * 64;
        const uint32_t base = sW + (uint32_t)((d % 3) * 16384);
        #pragma unroll
        for (int i = 0; i < 4; i++) {
            int idx = tid + i * 256, r = idx >> 4, q = idx & 15;
            uint32_t off = (uint32_t)((q>>3)*8192) + SWZ128((uint32_t)(r*128 + (q&7)*16));
            CP_ASYNC16(base + off, &WOT[(size_t)(d0 + r) * DH + q*4]);
        }
    };

    #pragma unroll
    for (int i = 0; i < 8; i++) {
        int idx = tid + i * 256, r = idx >> 4, q = idx & 15;
        uint32_t off = (uint32_t)((q>>3)*16384) + SWZ128((uint32_t)(r*128 + (q&7)*16));
        CP_ASYNC16(sZ + off, &g_z[((size_t)h*SQ + s0 + r) * DH + q*4]);
    }
    prefetch_w(0);
    CP_COMMIT();
    prefetch_w(1);
    CP_COMMIT();

    const int r0 = mw + (lane >> 2);
    const int ec = (lane & 3) * 2;

    #pragma unroll 1
    for (int d = 0; d < 16; d++) {
        CP_WAIT(1);
        __syncthreads();
        if (d + 2 < 16) prefetch_w(d + 2);
        CP_COMMIT();

        const uint32_t sbW = sW + (uint32_t)((d % 3) * 16384);
        float acc[8][4] = {};

        #pragma unroll
        for (int ks = 0; ks < 8; ks++) {
            uint32_t a[4];
            {
                int row = mw + ((g & 1) << 3) + l7;
                int byo = (ks & 3)*32 + ((g >> 1) << 4);
                ldsm_x4(a[0], a[1], a[2], a[3],
                        sZ + (uint32_t)((ks >> 2)*16384) + SWZ128((uint32_t)(row*128 + byo)));
            }
            uint32_t b[16];
            #pragma unroll
            for (int nb = 0; nb < 4; nb++) {
                int row = nb * 16 + ((g >> 1) << 3) + l7;
                int byo = (ks & 3)*32 + ((g & 1) << 4);
                ldsm_x4(b[nb*4+0], b[nb*4+1], b[nb*4+2], b[nb*4+3],
                        sbW + (uint32_t)((ks >> 2)*8192) + SWZ128((uint32_t)(row*128 + byo)));
            }
            #pragma unroll
            for (int ni = 0; ni < 8; ni++)
                mma_tf32(acc[ni], a, b[(ni >> 1)*4 + (ni & 1)*2],
                                     b[(ni >> 1)*4 + (ni & 1)*2 + 1]);
        }

        const int d0 = d * 64;
        #pragma unroll
        for (int ni = 0; ni < 8; ni++) {
            int dg = d0 + ni*8 + ec;
            float b0 = bO[dg] * 0.0625f, b1 = bO[dg + 1] * 0.0625f;
            int sg0 = s0 + r0, sg1 = sg0 + 8;
            *(float2*)&out[((size_t)sg0 * NH + h) * DM + dg] =
                make_float2(acc[ni][0] + b0, acc[ni][1] + b1);
            *(float2*)&out[((size_t)sg1 * NH + h) * DM + dg] =
                make_float2(acc[ni][2] + b0, acc[ni][3] + b1);
        }
    }
}

// -------------------------------------------------------------------------------
extern "C" void kernel_launch(void* const* d_in, const int* in_sizes, int n_in,
                              void* d_out, int out_size)
{
    (void)in_sizes; (void)n_in; (void)out_size;
    const float* xq = (const float*)d_in[0];
    const float* xk = (const float*)d_in[1];
    const float* xv = (const float*)d_in[2];
    const float* WQ = (const float*)d_in[3];
    const float* bQ = (const float*)d_in[4];
    const float* WK = (const float*)d_in[5];
    const float* bK = (const float*)d_in[6];
    const float* WV = (const float*)d_in[7];
    const float* bV = (const float*)d_in[8];
    const float* WO = (const float*)d_in[9];
    const float* bO = (const float*)d_in[10];
    float* out = (float*)d_out;

    static int smem_set = 0;
    if (!smem_set) {
        cudaFuncSetAttribute(attn_mma_kernel,
                             cudaFuncAttributeMaxDynamicSharedMemorySize, 40960);
        cudaFuncSetAttribute(proj_mma_kernel,
                             cudaFuncAttributeMaxDynamicSharedMemorySize, 49152);
        cudaFuncSetAttribute(outproj_mma_kernel,
                             cudaFuncAttributeMaxDynamicSharedMemorySize, 81920);
        smem_set = 1;
    }

    rope_tab_kernel<<<256, 256>>>();
    transpose_w_kernel<<<dim3(64, 64), dim3(32, 8)>>>(WQ, WK, WV, WO);
    proj_mma_kernel<<<dim3(16, 16, 3), 256, 49152>>>(xq, xk, xv, bQ, bK, bV);
    attn_mma_kernel<<<dim3(16, 16), 128, 40960>>>();
    outproj_mma_kernel<<<dim3(16, 16), 256, 81920>>>(bO, out);
}

// round 15
// speedup vs baseline: 1.0417x; 1.0417x over previous
#include <cuda_runtime.h>
#include <cuda_fp16.h>
#include <cstdint>
#include <math.h>

#define SQ 2048
#define NH 16
#define DM 1024
#define DH 64

__device__ __half g_q[NH * SQ * DH];      // pre-scaled by log2e/8, fp16
__device__ __half g_k[NH * SQ * DH];      // fp16
__device__ __half g_vt[NH * DH * SQ];     // V^T: [h][e][s], fp16
__device__ float  g_z[NH * SQ * DH];
__device__ float  g_wt[3][NH * DH * DM];  // W^T, tf32-rounded
__device__ float  g_wot[NH * DM * DH];    // W_O^T, tf32-rounded
__device__ float2 g_rope[SQ * 32];        // (sin, cos) per (pos, j)

__device__ __forceinline__ uint32_t smem_u32(const void* p) {
    uint32_t a;
    asm("{ .reg .u64 t; cvta.to.shared.u64 t, %1; cvt.u32.u64 %0, t; }" : "=r"(a) : "l"(p));
    return a;
}
#define SWZ128(x) ((x) ^ (((x) >> 3) & 0x70))

__device__ __forceinline__ float to_tf32(float x) {
    float y;
    asm("cvt.rna.tf32.f32 %0, %1;" : "=f"(y) : "f"(x));
    return y;
}
__device__ __forceinline__ float ex2(float x) {
    float y;
    asm("ex2.approx.ftz.f32 %0, %1;" : "=f"(y) : "f"(x));
    return y;
}
__device__ __forceinline__ uint32_t packh2(float lo, float hi) {
    uint32_t r;
    asm("cvt.rn.f16x2.f32 %0, %1, %2;" : "=r"(r) : "f"(hi), "f"(lo));
    return r;
}
__device__ __forceinline__ uint32_t h2ex2(uint32_t x) {
    uint32_t y;
    asm("ex2.approx.f16x2 %0, %1;" : "=r"(y) : "r"(x));
    return y;
}
__device__ __forceinline__ void ldsm_x4(uint32_t& r0, uint32_t& r1, uint32_t& r2,
                                        uint32_t& r3, uint32_t addr) {
    asm volatile("ldmatrix.sync.aligned.m8n8.x4.shared.b16 {%0,%1,%2,%3}, [%4];"
                 : "=r"(r0), "=r"(r1), "=r"(r2), "=r"(r3) : "r"(addr));
}
__device__ __forceinline__ void mma_tf32(float* c, const uint32_t* a,
                                         uint32_t b0, uint32_t b1) {
    asm volatile(
        "mma.sync.aligned.m16n8k8.row.col.f32.tf32.tf32.f32 "
        "{%0,%1,%2,%3}, {%4,%5,%6,%7}, {%8,%9}, {%0,%1,%2,%3};"
        : "+f"(c[0]), "+f"(c[1]), "+f"(c[2]), "+f"(c[3])
        : "r"(a[0]), "r"(a[1]), "r"(a[2]), "r"(a[3]), "r"(b0), "r"(b1));
}
__device__ __forceinline__ void mma_f16(float* c, const uint32_t* a,
                                        uint32_t b0, uint32_t b1) {
    asm volatile(
        "mma.sync.aligned.m16n8k16.row.col.f32.f16.f16.f32 "
        "{%0,%1,%2,%3}, {%4,%5,%6,%7}, {%8,%9}, {%0,%1,%2,%3};"
        : "+f"(c[0]), "+f"(c[1]), "+f"(c[2]), "+f"(c[3])
        : "r"(a[0]), "r"(a[1]), "r"(a[2]), "r"(a[3]), "r"(b0), "r"(b1));
}
#define CP_ASYNC16(dst, src) \
    asm volatile("cp.async.cg.shared.global [%0], [%1], 16;" :: "r"(dst), "l"(src))
#define CP_COMMIT() asm volatile("cp.async.commit_group;" ::: "memory")
#define CP_WAIT(n)  asm volatile("cp.async.wait_group %0;" :: "n"(n) : "memory")

// ---------------- RoPE table ----------------------------------------------------
__global__ void rope_tab_kernel()
{
    const int idx = blockIdx.x * 256 + threadIdx.x;
    const int pos = idx >> 5, j = idx & 31;
    const float L2B = 0.41524101186092029f;           // log2(10000)/32
    float invf = exp2f(-(float)j * L2B);
    float sn, cs;
    sincosf((float)pos * invf, &sn, &cs);
    g_rope[idx] = make_float2(sn, cs);
}

// ---------------- W transpose (+tf32 round) -----------------------------------
__global__ void transpose_w_kernel(const float* __restrict__ WQ, const float* __restrict__ WK,
                                   const float* __restrict__ WV, const float* __restrict__ WO)
{
    __shared__ float t[32][33];
    const int m = blockIdx.y >> 4, h = blockIdx.y & 15;
    const float* src; float* dst; int R, C;
    if (m == 0)      { src = WQ + (size_t)h*DM*DH; dst = g_wt[0] + (size_t)h*DH*DM; R = DM; C = DH; }
    else if (m == 1) { src = WK + (size_t)h*DM*DH; dst = g_wt[1] + (size_t)h*DH*DM; R = DM; C = DH; }
    else if (m == 2) { src = WV + (size_t)h*DM*DH; dst = g_wt[2] + (size_t)h*DH*DM; R = DM; C = DH; }
    else             { src = WO + (size_t)h*DH*DM; dst = g_wot   + (size_t)h*DM*DH; R = DH; C = DM; }
    const int nrt = R / 32, rt = blockIdx.x % nrt, ct = blockIdx.x / nrt;
    const int x = ct * 32 + threadIdx.x;
    #pragma unroll
    for (int j = 0; j < 4; j++)
        t[threadIdx.y + j*8][threadIdx.x] =
            to_tf32(src[(size_t)(rt*32 + threadIdx.y + j*8) * C + x]);
    __syncthreads();
    const int xo = rt * 32 + threadIdx.x;
    #pragma unroll
    for (int j = 0; j < 4; j++)
        dst[(size_t)(ct*32 + threadIdx.y + j*8) * R + xo] = t[threadIdx.x][threadIdx.y + j*8];
}

// ---------------- Projection via HMMA tf32, 4-stage cp.async (R13 shape) -------
__global__ __launch_bounds__(256, 1) void proj_mma_kernel(
    const float* __restrict__ xq, const float* __restrict__ xk, const float* __restrict__ xv,
    const float* __restrict__ bQ, const float* __restrict__ bK, const float* __restrict__ bV)
{
    extern __shared__ uint8_t dsm[];
    const uint32_t sA = smem_u32(dsm);
    const uint32_t sB = sA + 65536;

    const int tid = threadIdx.x, w = tid >> 5, lane = tid & 31;
    const int h = blockIdx.y, which = blockIdx.z;
    const int s0 = blockIdx.x * 128;

    const float* X    = (which == 0) ? xq : (which == 1) ? xk : xv;
    const float* bias = (which == 0) ? bQ : (which == 1) ? bK : bV;
    const float* WT   = g_wt[which] + (size_t)h * DH * DM;

    const int mw = w * 16;
    const int g  = lane >> 3, l7 = lane & 7;

    auto prefetch = [&](int c) {
        const int k0 = c * 32;
        const uint32_t ab = sA + (uint32_t)((c & 3) * 16384);
        const uint32_t bb = sB + (uint32_t)((c & 3) * 8192);
        #pragma unroll
        for (int i = 0; i < 4; i++) {
            int idx = tid + i * 256, r = idx >> 3, q = idx & 7;
            CP_ASYNC16(ab + SWZ128((uint32_t)(r*128 + q*16)),
                       &X[(((size_t)(s0 + r)) * NH + h) * DM + k0 + q*4]);
        }
        #pragma unroll
        for (int i = 0; i < 2; i++) {
            int idx = tid + i * 256, n = idx >> 3, q = idx & 7;
            CP_ASYNC16(bb + SWZ128((uint32_t)(n*128 + q*16)),
                       &WT[(size_t)n * DM + k0 + q*4]);
        }
    };

    float acc[8][4] = {};

    prefetch(0); CP_COMMIT();
    prefetch(1); CP_COMMIT();
    prefetch(2); CP_COMMIT();

    #pragma unroll 1
    for (int c = 0; c < 32; c++) {
        CP_WAIT(2);
        __syncthreads();
        if (c + 3 < 32) prefetch(c + 3);
        CP_COMMIT();

        const uint32_t sbA = sA + (uint32_t)((c & 3) * 16384);
        const uint32_t sbB = sB + (uint32_t)((c & 3) * 8192);
        #pragma unroll
        for (int kk = 0; kk < 4; kk++) {
            const int kb = kk * 32;
            uint32_t a[4];
            {
                int row = mw + ((g & 1) << 3) + l7;
                int byo = kb + ((g >> 1) << 4);
                ldsm_x4(a[0], a[1], a[2], a[3], sbA + SWZ128((uint32_t)(row*128 + byo)));
            }
            uint32_t b[16];
            #pragma unroll
            for (int nb = 0; nb < 4; nb++) {
                int row = nb * 16 + ((g >> 1) << 3) + l7;
                int byo = kb + ((g & 1) << 4);
                ldsm_x4(b[nb*4+0], b[nb*4+1], b[nb*4+2], b[nb*4+3],
                        sbB + SWZ128((uint32_t)(row*128 + byo)));
            }
            #pragma unroll
            for (int ni = 0; ni < 8; ni++)
                mma_tf32(acc[ni], a, b[(ni >> 1)*4 + (ni & 1)*2],
                                     b[(ni >> 1)*4 + (ni & 1)*2 + 1]);
        }
    }

    const int r0 = mw + (lane >> 2);
    const int ec = (lane & 3) * 2;

    #pragma unroll
    for (int ni = 0; ni < 8; ni++) {
        float bv0 = bias[h * DH + ni*8 + ec];
        float bv1 = bias[h * DH + ni*8 + ec + 1];
        acc[ni][0] += bv0; acc[ni][1] += bv1;
        acc[ni][2] += bv0; acc[ni][3] += bv1;
    }

    if (which < 2) {
        #pragma unroll
        for (int ni = 0; ni < 4; ni++) {
            #pragma unroll
            for (int cc = 0; cc < 2; cc++) {
                int j = ni*8 + ec + cc;
                #pragma unroll
                for (int rr = 0; rr < 2; rr++) {
                    float2 sc = g_rope[(s0 + r0 + rr*8) * 32 + j];
                    int ci = rr*2 + cc;
                    float x = acc[ni][ci], y = acc[ni+4][ci];
                    acc[ni][ci]   = x*sc.y - y*sc.x;
                    acc[ni+4][ci] = y*sc.y + x*sc.x;
                }
            }
        }
    }

    if (which == 2) {
        #pragma unroll
        for (int ni = 0; ni < 8; ni++) {
            int e = ni*8 + ec;
            int sg0 = s0 + r0, sg1 = sg0 + 8;
            g_vt[((size_t)h*DH + e    ) * SQ + sg0] = __float2half_rn(acc[ni][0]);
            g_vt[((size_t)h*DH + e + 1) * SQ + sg0] = __float2half_rn(acc[ni][1]);
            g_vt[((size_t)h*DH + e    ) * SQ + sg1] = __float2half_rn(acc[ni][2]);
            g_vt[((size_t)h*DH + e + 1) * SQ + sg1] = __float2half_rn(acc[ni][3]);
        }
    } else {
        const float osc = (which == 0) ? 0.18033688011112042f : 1.0f;   // log2e/8
        __half* out = (which == 0) ? g_q : g_k;
        #pragma unroll
        for (int ni = 0; ni < 8; ni++) {
            int e = ni*8 + ec;
            *(uint32_t*)&out[((size_t)h*SQ + s0 + r0    ) * DH + e] =
                packh2(acc[ni][0]*osc, acc[ni][1]*osc);
            *(uint32_t*)&out[((size_t)h*SQ + s0 + r0 + 8) * DH + e] =
                packh2(acc[ni][2]*osc, acc[ni][3]*osc);
        }
    }
}

// ---------------- Attention: fp16 HMMA; 3-stage KV pipeline ---------------------
// dyn smem: Q @0 (8KB), K @8192 (3x8KB), V @32768 (3x8KB) = 56KB; 2 CTAs/SM
__global__ __launch_bounds__(128, 2) void attn_mma_kernel()
{
    extern __shared__ uint8_t dsm[];
    const uint32_t sQ = smem_u32(dsm);
    const uint32_t sK = sQ + 8192;
    const uint32_t sV = sQ + 32768;

    const int tid = threadIdx.x, w = tid >> 5, lane = tid & 31;
    const int h = blockIdx.y;
    const int g = lane >> 3, l7 = lane & 7;
    const int mw = w * 16;
    const int r_loc = lane >> 2, ec = (lane & 3) * 2;
    const uint32_t H2ONE = 0x3C003C00u;

    auto load_kv = [&](int kt) {
        const int kk0 = kt * 64;
        const uint32_t boff = (uint32_t)((kt % 3) * 8192);
        #pragma unroll
        for (int i = 0; i < 4; i++) {
            int idx = tid + i * 128, r = idx >> 3, q = idx & 7;
            uint32_t off = boff + SWZ128((uint32_t)(r*128 + q*16));
            CP_ASYNC16(sK + off, &g_k [((size_t)h*SQ + kk0 + r) * DH + q*8]);
            CP_ASYNC16(sV + off, &g_vt[((size_t)h*DH + r) * SQ + kk0 + q*8]);
        }
    };

    for (int rep = 0; rep < 2; rep++) {
        const int qb = rep ? (31 - (int)blockIdx.x) : (int)blockIdx.x;
        const int q0 = qb * 64;

        __syncthreads();
        #pragma unroll
        for (int i = 0; i < 4; i++) {
            int idx = tid + i * 128, r = idx >> 3, q = idx & 7;
            CP_ASYNC16(sQ + SWZ128((uint32_t)(r*128 + q*16)),
                       &g_q[((size_t)h*SQ + q0 + r) * DH + q*8]);
        }
        CP_COMMIT();
        load_kv(0);
        CP_COMMIT();
        if (qb >= 1) load_kv(1);
        CP_COMMIT();
        CP_WAIT(2);          // Q landed (kv0, kv1 may be in flight)
        __syncthreads();

        uint32_t qa[4][4];
        #pragma unroll
        for (int kc = 0; kc < 4; kc++) {
            int row = mw + ((g & 1) << 3) + l7;
            int byo = kc*32 + ((g >> 1) << 4);
            ldsm_x4(qa[kc][0], qa[kc][1], qa[kc][2], qa[kc][3],
                    sQ + SWZ128((uint32_t)(row*128 + byo)));
        }

        float m0 = -1e30f, m1 = -1e30f, l0 = 0.f, l1 = 0.f;
        float oa[8][4] = {};

        for (int kt = 0; kt <= qb; kt++) {
            const uint32_t kb_off = (uint32_t)((kt % 3) * 8192);
            CP_WAIT(1);      // tile kt complete; kt+1 may remain in flight
            __syncthreads();
            if (kt + 2 <= qb) load_kv(kt + 2);
            CP_COMMIT();

            float sacc[8][4] = {};
            #pragma unroll
            for (int kc = 0; kc < 4; kc++) {
                uint32_t b[16];
                #pragma unroll
                for (int nb = 0; nb < 4; nb++) {
                    int row = nb*16 + ((g >> 1) << 3) + l7;
                    int byo = kc*32 + ((g & 1) << 4);
                    ldsm_x4(b[nb*4+0], b[nb*4+1], b[nb*4+2], b[nb*4+3],
                            sK + kb_off + SWZ128((uint32_t)(row*128 + byo)));
                }
                #pragma unroll
                for (int ni = 0; ni < 8; ni++)
                    mma_f16(sacc[ni], qa[kc], b[(ni>>1)*4 + (ni&1)*2],
                                              b[(ni>>1)*4 + (ni&1)*2 + 1]);
            }

            const bool diag = (kt == qb);
            if (diag) {
                #pragma unroll
                for (int ni = 0; ni < 8; ni++) {
                    int col = ni*8 + ec;
                    int row0 = mw + r_loc, row1 = row0 + 8;
                    if (col     > row0) sacc[ni][0] = -1e30f;
                    if (col + 1 > row0) sacc[ni][1] = -1e30f;
                    if (col     > row1) sacc[ni][2] = -1e30f;
                    if (col + 1 > row1) sacc[ni][3] = -1e30f;
                }
            }

            float rx0 = -1e30f, rx1 = -1e30f;
            #pragma unroll
            for (int ni = 0; ni < 8; ni++) {
                rx0 = fmaxf(rx0, fmaxf(sacc[ni][0], sacc[ni][1]));
                rx1 = fmaxf(rx1, fmaxf(sacc[ni][2], sacc[ni][3]));
            }
            rx0 = fmaxf(rx0, __shfl_xor_sync(0xffffffffu, rx0, 1));
            rx0 = fmaxf(rx0, __shfl_xor_sync(0xffffffffu, rx0, 2));
            rx1 = fmaxf(rx1, __shfl_xor_sync(0xffffffffu, rx1, 1));
            rx1 = fmaxf(rx1, __shfl_xor_sync(0xffffffffu, rx1, 2));
            float mn0 = fmaxf(m0, rx0), mn1 = fmaxf(m1, rx1);
            float c0 = ex2(m0 - mn0), c1 = ex2(m1 - mn1);

            uint32_t prow0[8], prow1[8];
            #pragma unroll
            for (int ni = 0; ni < 8; ni++) {
                prow0[ni] = h2ex2(packh2(sacc[ni][0] - mn0, sacc[ni][1] - mn0));
                prow1[ni] = h2ex2(packh2(sacc[ni][2] - mn1, sacc[ni][3] - mn1));
            }

            m0 = mn0; m1 = mn1;
            #pragma unroll
            for (int ni = 0; ni < 8; ni++) {
                oa[ni][0] *= c0; oa[ni][1] *= c0;
                oa[ni][2] *= c1; oa[ni][3] *= c1;
            }

            float lacc[4] = {};
            #pragma unroll
            for (int ks = 0; ks < 4; ks++) {
                uint32_t a[4];
                a[0] = prow0[2*ks];
                a[1] = prow1[2*ks];
                a[2] = prow0[2*ks+1];
                a[3] = prow1[2*ks+1];

                mma_f16(lacc, a, H2ONE, H2ONE);

                uint32_t b[16];
                #pragma unroll
                for (int nb = 0; nb < 4; nb++) {
                    int rowb = nb*16 + ((g >> 1) << 3) + l7;
                    int byob = ks*32 + ((g & 1) << 4);
                    ldsm_x4(b[nb*4+0], b[nb*4+1], b[nb*4+2], b[nb*4+3],
                            sV + kb_off + SWZ128((uint32_t)(rowb*128 + byob)));
                }
                #pragma unroll
                for (int ni = 0; ni < 8; ni++)
                    mma_f16(oa[ni], a, b[(ni>>1)*4 + (ni&1)*2],
                                       b[(ni>>1)*4 + (ni&1)*2 + 1]);
            }
            l0 = l0 * c0 + lacc[0];
            l1 = l1 * c1 + lacc[2];
        }

        float inv0 = 1.f / l0, inv1 = 1.f / l1;
        int row0 = q0 + mw + r_loc;
        #pragma unroll
        for (int ni = 0; ni < 8; ni++) {
            int e = ni*8 + ec;
            *(float2*)&g_z[((size_t)h*SQ + row0    ) * DH + e] =
                make_float2(to_tf32(oa[ni][0]*inv0), to_tf32(oa[ni][1]*inv0));
            *(float2*)&g_z[((size_t)h*SQ + row0 + 8) * DH + e] =
                make_float2(to_tf32(oa[ni][2]*inv1), to_tf32(oa[ni][3]*inv1));
        }
    }
}

// ---------------- Output projection, persistent, d-tile 64, 2 CTAs/SM -----------
// dyn smem: Z @0 (32KB), W @32768 (3x16KB) = 80KB
__global__ __launch_bounds__(256, 2) void outproj_mma_kernel(
    const float* __restrict__ bO, float* __restrict__ out)
{
    extern __shared__ uint8_t dsm[];
    const uint32_t sZ = smem_u32(dsm);
    const uint32_t sW = sZ + 32768;

    const int tid = threadIdx.x, w = tid >> 5, lane = tid & 31;
    const int s0 = blockIdx.x * 128, h = blockIdx.y;
    const float* WOT = g_wot + (size_t)h * DM * DH;

    const int mw = w * 16;
    const int g  = lane >> 3, l7 = lane & 7;

    auto prefetch_w = [&](int d) {
        const int d0 = d * 64;
        const uint32_t base = sW + (uint32_t)((d % 3) * 16384);
        #pragma unroll
        for (int i = 0; i < 4; i++) {
            int idx = tid + i * 256, r = idx >> 4, q = idx & 15;
            uint32_t off = (uint32_t)((q>>3)*8192) + SWZ128((uint32_t)(r*128 + (q&7)*16));
            CP_ASYNC16(base + off, &WOT[(size_t)(d0 + r) * DH + q*4]);
        }
    };

    #pragma unroll
    for (int i = 0; i < 8; i++) {
        int idx = tid + i * 256, r = idx >> 4, q = idx & 15;
        uint32_t off = (uint32_t)((q>>3)*16384) + SWZ128((uint32_t)(r*128 + (q&7)*16));
        CP_ASYNC16(sZ + off, &g_z[((size_t)h*SQ + s0 + r) * DH + q*4]);
    }
    prefetch_w(0);
    CP_COMMIT();
    prefetch_w(1);
    CP_COMMIT();

    const int r0 = mw + (lane >> 2);
    const int ec = (lane & 3) * 2;

    #pragma unroll 1
    for (int d = 0; d < 16; d++) {
        CP_WAIT(1);
        __syncthreads();
        if (d + 2 < 16) prefetch_w(d + 2);
        CP_COMMIT();

        const uint32_t sbW = sW + (uint32_t)((d % 3) * 16384);
        float acc[8][4] = {};

        #pragma unroll
        for (int ks = 0; ks < 8; ks++) {
            uint32_t a[4];
            {
                int row = mw + ((g & 1) << 3) + l7;
                int byo = (ks & 3)*32 + ((g >> 1) << 4);
                ldsm_x4(a[0], a[1], a[2], a[3],
                        sZ + (uint32_t)((ks >> 2)*16384) + SWZ128((uint32_t)(row*128 + byo)));
            }
            uint32_t b[16];
            #pragma unroll
            for (int nb = 0; nb < 4; nb++) {
                int row = nb * 16 + ((g >> 1) << 3) + l7;
                int byo = (ks & 3)*32 + ((g & 1) << 4);
                ldsm_x4(b[nb*4+0], b[nb*4+1], b[nb*4+2], b[nb*4+3],
                        sbW + (uint32_t)((ks >> 2)*8192) + SWZ128((uint32_t)(row*128 + byo)));
            }
            #pragma unroll
            for (int ni = 0; ni < 8; ni++)
                mma_tf32(acc[ni], a, b[(ni >> 1)*4 + (ni & 1)*2],
                                     b[(ni >> 1)*4 + (ni & 1)*2 + 1]);
        }

        const int d0 = d * 64;
        #pragma unroll
        for (int ni = 0; ni < 8; ni++) {
            int dg = d0 + ni*8 + ec;
            float b0 = bO[dg] * 0.0625f, b1 = bO[dg + 1] * 0.0625f;
            int sg0 = s0 + r0, sg1 = sg0 + 8;
            *(float2*)&out[((size_t)sg0 * NH + h) * DM + dg] =
                make_float2(acc[ni][0] + b0, acc[ni][1] + b1);
            *(float2*)&out[((size_t)sg1 * NH + h) * DM + dg] =
                make_float2(acc[ni][2] + b0, acc[ni][3] + b1);
        }
    }
}

// -------------------------------------------------------------------------------
extern "C" void kernel_launch(void* const* d_in, const int* in_sizes, int n_in,
                              void* d_out, int out_size)
{
    (void)in_sizes; (void)n_in; (void)out_size;
    const float* xq = (const float*)d_in[0];
    const float* xk = (const float*)d_in[1];
    const float* xv = (const float*)d_in[2];
    const float* WQ = (const float*)d_in[3];
    const float* bQ = (const float*)d_in[4];
    const float* WK = (const float*)d_in[5];
    const float* bK = (const float*)d_in[6];
    const float* WV = (const float*)d_in[7];
    const float* bV = (const float*)d_in[8];
    const float* WO = (const float*)d_in[9];
    const float* bO = (const float*)d_in[10];
    float* out = (float*)d_out;

    static int smem_set = 0;
    if (!smem_set) {
        cudaFuncSetAttribute(attn_mma_kernel,
                             cudaFuncAttributeMaxDynamicSharedMemorySize, 57344);
        cudaFuncSetAttribute(proj_mma_kernel,
                             cudaFuncAttributeMaxDynamicSharedMemorySize, 98304);
        cudaFuncSetAttribute(outproj_mma_kernel,
                             cudaFuncAttributeMaxDynamicSharedMemorySize, 81920);
        smem_set = 1;
    }

    rope_tab_kernel<<<256, 256>>>();
    transpose_w_kernel<<<dim3(64, 64), dim3(32, 8)>>>(WQ, WK, WV, WO);
    proj_mma_kernel<<<dim3(16, 16, 3), 256, 98304>>>(xq, xk, xv, bQ, bK, bV);
    attn_mma_kernel<<<dim3(16, 16), 128, 57344>>>();
    outproj_mma_kernel<<<dim3(16, 16), 256, 81920>>>(bO, out);
}

// round 16
// speedup vs baseline: 1.1341x; 1.0888x over previous
#include <cuda_runtime.h>
#include <cuda_fp16.h>
#include <cstdint>
#include <math.h>

#define SQ 2048
#define NH 16
#define DM 1024
#define DH 64

__device__ __half g_q[NH * SQ * DH];      // pre-scaled by log2e/8, fp16
__device__ __half g_k[NH * SQ * DH];      // fp16
__device__ __half g_vt[NH * DH * SQ];     // V^T: [h][e][s], fp16
__device__ __half g_z[NH * SQ * DH];      // fp16
__device__ float  g_wt[3][NH * DH * DM];  // W^T, tf32-rounded
__device__ __half g_wot[NH * DM * DH];    // W_O^T, fp16
__device__ float2 g_rope[SQ * 32];        // (sin, cos) per (pos, j)

__device__ __forceinline__ uint32_t smem_u32(const void* p) {
    uint32_t a;
    asm("{ .reg .u64 t; cvta.to.shared.u64 t, %1; cvt.u32.u64 %0, t; }" : "=r"(a) : "l"(p));
    return a;
}
#define SWZ128(x) ((x) ^ (((x) >> 3) & 0x70))

__device__ __forceinline__ float to_tf32(float x) {
    float y;
    asm("cvt.rna.tf32.f32 %0, %1;" : "=f"(y) : "f"(x));
    return y;
}
__device__ __forceinline__ float ex2(float x) {
    float y;
    asm("ex2.approx.ftz.f32 %0, %1;" : "=f"(y) : "f"(x));
    return y;
}
__device__ __forceinline__ uint32_t packh2(float lo, float hi) {
    uint32_t r;
    asm("cvt.rn.f16x2.f32 %0, %1, %2;" : "=r"(r) : "f"(hi), "f"(lo));
    return r;
}
__device__ __forceinline__ uint32_t h2ex2(uint32_t x) {
    uint32_t y;
    asm("ex2.approx.f16x2 %0, %1;" : "=r"(y) : "r"(x));
    return y;
}
__device__ __forceinline__ void ldsm_x4(uint32_t& r0, uint32_t& r1, uint32_t& r2,
                                        uint32_t& r3, uint32_t addr) {
    asm volatile("ldmatrix.sync.aligned.m8n8.x4.shared.b16 {%0,%1,%2,%3}, [%4];"
                 : "=r"(r0), "=r"(r1), "=r"(r2), "=r"(r3) : "r"(addr));
}
__device__ __forceinline__ void mma_tf32(float* c, const uint32_t* a,
                                         uint32_t b0, uint32_t b1) {
    asm volatile(
        "mma.sync.aligned.m16n8k8.row.col.f32.tf32.tf32.f32 "
        "{%0,%1,%2,%3}, {%4,%5,%6,%7}, {%8,%9}, {%0,%1,%2,%3};"
        : "+f"(c[0]), "+f"(c[1]), "+f"(c[2]), "+f"(c[3])
        : "r"(a[0]), "r"(a[1]), "r"(a[2]), "r"(a[3]), "r"(b0), "r"(b1));
}
__device__ __forceinline__ void mma_f16(float* c, const uint32_t* a,
                                        uint32_t b0, uint32_t b1) {
    asm volatile(
        "mma.sync.aligned.m16n8k16.row.col.f32.f16.f16.f32 "
        "{%0,%1,%2,%3}, {%4,%5,%6,%7}, {%8,%9}, {%0,%1,%2,%3};"
        : "+f"(c[0]), "+f"(c[1]), "+f"(c[2]), "+f"(c[3])
        : "r"(a[0]), "r"(a[1]), "r"(a[2]), "r"(a[3]), "r"(b0), "r"(b1));
}
#define CP_ASYNC16(dst, src) \
    asm volatile("cp.async.cg.shared.global [%0], [%1], 16;" :: "r"(dst), "l"(src))
#define CP_COMMIT() asm volatile("cp.async.commit_group;" ::: "memory")
#define CP_WAIT(n)  asm volatile("cp.async.wait_group %0;" :: "n"(n) : "memory")

// ---------------- RoPE table ----------------------------------------------------
__global__ void rope_tab_kernel()
{
    const int idx = blockIdx.x * 256 + threadIdx.x;
    const int pos = idx >> 5, j = idx & 31;
    const float L2B = 0.41524101186092029f;           // log2(10000)/32
    float invf = exp2f(-(float)j * L2B);
    float sn, cs;
    sincosf((float)pos * invf, &sn, &cs);
    g_rope[idx] = make_float2(sn, cs);
}

// ---------------- W transpose: W_{Q,K,V} -> tf32 float; W_O -> fp16 -------------
__global__ void transpose_w_kernel(const float* __restrict__ WQ, const float* __restrict__ WK,
                                   const float* __restrict__ WV, const float* __restrict__ WO)
{
    __shared__ float t[32][33];
    const int m = blockIdx.y >> 4, h = blockIdx.y & 15;
    const float* src; float* dst = nullptr; int R, C;
    if (m == 0)      { src = WQ + (size_t)h*DM*DH; dst = g_wt[0] + (size_t)h*DH*DM; R = DM; C = DH; }
    else if (m == 1) { src = WK + (size_t)h*DM*DH; dst = g_wt[1] + (size_t)h*DH*DM; R = DM; C = DH; }
    else if (m == 2) { src = WV + (size_t)h*DM*DH; dst = g_wt[2] + (size_t)h*DH*DM; R = DM; C = DH; }
    else             { src = WO + (size_t)h*DH*DM; R = DH; C = DM; }
    const int nrt = R / 32, rt = blockIdx.x % nrt, ct = blockIdx.x / nrt;
    const int x = ct * 32 + threadIdx.x;
    if (m < 3) {
        #pragma unroll
        for (int j = 0; j < 4; j++)
            t[threadIdx.y + j*8][threadIdx.x] =
                to_tf32(src[(size_t)(rt*32 + threadIdx.y + j*8) * C + x]);
    } else {
        #pragma unroll
        for (int j = 0; j < 4; j++)
            t[threadIdx.y + j*8][threadIdx.x] =
                src[(size_t)(rt*32 + threadIdx.y + j*8) * C + x];
    }
    __syncthreads();
    const int xo = rt * 32 + threadIdx.x;
    if (m < 3) {
        #pragma unroll
        for (int j = 0; j < 4; j++)
            dst[(size_t)(ct*32 + threadIdx.y + j*8) * R + xo] = t[threadIdx.x][threadIdx.y + j*8];
    } else {
        __half* dsth = g_wot + (size_t)h*DM*DH;
        #pragma unroll
        for (int j = 0; j < 4; j++)
            dsth[(size_t)(ct*32 + threadIdx.y + j*8) * R + xo] =
                __float2half_rn(t[threadIdx.x][threadIdx.y + j*8]);
    }
}

// ---------------- Projection via HMMA tf32, 4-stage cp.async (R13 shape) -------
__global__ __launch_bounds__(256, 1) void proj_mma_kernel(
    const float* __restrict__ xq, const float* __restrict__ xk, const float* __restrict__ xv,
    const float* __restrict__ bQ, const float* __restrict__ bK, const float* __restrict__ bV)
{
    extern __shared__ uint8_t dsm[];
    const uint32_t sA = smem_u32(dsm);
    const uint32_t sB = sA + 65536;

    const int tid = threadIdx.x, w = tid >> 5, lane = tid & 31;
    const int h = blockIdx.y, which = blockIdx.z;
    const int s0 = blockIdx.x * 128;

    const float* X    = (which == 0) ? xq : (which == 1) ? xk : xv;
    const float* bias = (which == 0) ? bQ : (which == 1) ? bK : bV;
    const float* WT   = g_wt[which] + (size_t)h * DH * DM;

    const int mw = w * 16;
    const int g  = lane >> 3, l7 = lane & 7;

    auto prefetch = [&](int c) {
        const int k0 = c * 32;
        const uint32_t ab = sA + (uint32_t)((c & 3) * 16384);
        const uint32_t bb = sB + (uint32_t)((c & 3) * 8192);
        #pragma unroll
        for (int i = 0; i < 4; i++) {
            int idx = tid + i * 256, r = idx >> 3, q = idx & 7;
            CP_ASYNC16(ab + SWZ128((uint32_t)(r*128 + q*16)),
                       &X[(((size_t)(s0 + r)) * NH + h) * DM + k0 + q*4]);
        }
        #pragma unroll
        for (int i = 0; i < 2; i++) {
            int idx = tid + i * 256, n = idx >> 3, q = idx & 7;
            CP_ASYNC16(bb + SWZ128((uint32_t)(n*128 + q*16)),
                       &WT[(size_t)n * DM + k0 + q*4]);
        }
    };

    float acc[8][4] = {};

    prefetch(0); CP_COMMIT();
    prefetch(1); CP_COMMIT();
    prefetch(2); CP_COMMIT();

    #pragma unroll 1
    for (int c = 0; c < 32; c++) {
        CP_WAIT(2);
        __syncthreads();
        if (c + 3 < 32) prefetch(c + 3);
        CP_COMMIT();

        const uint32_t sbA = sA + (uint32_t)((c & 3) * 16384);
        const uint32_t sbB = sB + (uint32_t)((c & 3) * 8192);
        #pragma unroll
        for (int kk = 0; kk < 4; kk++) {
            const int kb = kk * 32;
            uint32_t a[4];
            {
                int row = mw + ((g & 1) << 3) + l7;
                int byo = kb + ((g >> 1) << 4);
                ldsm_x4(a[0], a[1], a[2], a[3], sbA + SWZ128((uint32_t)(row*128 + byo)));
            }
            uint32_t b[16];
            #pragma unroll
            for (int nb = 0; nb < 4; nb++) {
                int row = nb * 16 + ((g >> 1) << 3) + l7;
                int byo = kb + ((g & 1) << 4);
                ldsm_x4(b[nb*4+0], b[nb*4+1], b[nb*4+2], b[nb*4+3],
                        sbB + SWZ128((uint32_t)(row*128 + byo)));
            }
            #pragma unroll
            for (int ni = 0; ni < 8; ni++)
                mma_tf32(acc[ni], a, b[(ni >> 1)*4 + (ni & 1)*2],
                                     b[(ni >> 1)*4 + (ni & 1)*2 + 1]);
        }
    }

    const int r0 = mw + (lane >> 2);
    const int ec = (lane & 3) * 2;

    #pragma unroll
    for (int ni = 0; ni < 8; ni++) {
        float bv0 = bias[h * DH + ni*8 + ec];
        float bv1 = bias[h * DH + ni*8 + ec + 1];
        acc[ni][0] += bv0; acc[ni][1] += bv1;
        acc[ni][2] += bv0; acc[ni][3] += bv1;
    }

    if (which < 2) {
        #pragma unroll
        for (int ni = 0; ni < 4; ni++) {
            #pragma unroll
            for (int cc = 0; cc < 2; cc++) {
                int j = ni*8 + ec + cc;
                #pragma unroll
                for (int rr = 0; rr < 2; rr++) {
                    float2 sc = g_rope[(s0 + r0 + rr*8) * 32 + j];
                    int ci = rr*2 + cc;
                    float x = acc[ni][ci], y = acc[ni+4][ci];
                    acc[ni][ci]   = x*sc.y - y*sc.x;
                    acc[ni+4][ci] = y*sc.y + x*sc.x;
                }
            }
        }
    }

    if (which == 2) {
        #pragma unroll
        for (int ni = 0; ni < 8; ni++) {
            int e = ni*8 + ec;
            int sg0 = s0 + r0, sg1 = sg0 + 8;
            g_vt[((size_t)h*DH + e    ) * SQ + sg0] = __float2half_rn(acc[ni][0]);
            g_vt[((size_t)h*DH + e + 1) * SQ + sg0] = __float2half_rn(acc[ni][1]);
            g_vt[((size_t)h*DH + e    ) * SQ + sg1] = __float2half_rn(acc[ni][2]);
            g_vt[((size_t)h*DH + e + 1) * SQ + sg1] = __float2half_rn(acc[ni][3]);
        }
    } else {
        const float osc = (which == 0) ? 0.18033688011112042f : 1.0f;   // log2e/8
        __half* out = (which == 0) ? g_q : g_k;
        #pragma unroll
        for (int ni = 0; ni < 8; ni++) {
            int e = ni*8 + ec;
            *(uint32_t*)&out[((size_t)h*SQ + s0 + r0    ) * DH + e] =
                packh2(acc[ni][0]*osc, acc[ni][1]*osc);
            *(uint32_t*)&out[((size_t)h*SQ + s0 + r0 + 8) * DH + e] =
                packh2(acc[ni][2]*osc, acc[ni][3]*osc);
        }
    }
}

// ---------------- Attention: fp16 HMMA; 3-stage KV pipeline ---------------------
// dyn smem: Q @0 (8KB), K @8192 (3x8KB), V @32768 (3x8KB) = 56KB; 2 CTAs/SM
__global__ __launch_bounds__(128, 2) void attn_mma_kernel()
{
    extern __shared__ uint8_t dsm[];
    const uint32_t sQ = smem_u32(dsm);
    const uint32_t sK = sQ + 8192;
    const uint32_t sV = sQ + 32768;

    const int tid = threadIdx.x, w = tid >> 5, lane = tid & 31;
    const int h = blockIdx.y;
    const int g = lane >> 3, l7 = lane & 7;
    const int mw = w * 16;
    const int r_loc = lane >> 2, ec = (lane & 3) * 2;
    const uint32_t H2ONE = 0x3C003C00u;

    auto load_kv = [&](int kt) {
        const int kk0 = kt * 64;
        const uint32_t boff = (uint32_t)((kt % 3) * 8192);
        #pragma unroll
        for (int i = 0; i < 4; i++) {
            int idx = tid + i * 128, r = idx >> 3, q = idx & 7;
            uint32_t off = boff + SWZ128((uint32_t)(r*128 + q*16));
            CP_ASYNC16(sK + off, &g_k [((size_t)h*SQ + kk0 + r) * DH + q*8]);
            CP_ASYNC16(sV + off, &g_vt[((size_t)h*DH + r) * SQ + kk0 + q*8]);
        }
    };

    for (int rep = 0; rep < 2; rep++) {
        const int qb = rep ? (31 - (int)blockIdx.x) : (int)blockIdx.x;
        const int q0 = qb * 64;

        __syncthreads();
        #pragma unroll
        for (int i = 0; i < 4; i++) {
            int idx = tid + i * 128, r = idx >> 3, q = idx & 7;
            CP_ASYNC16(sQ + SWZ128((uint32_t)(r*128 + q*16)),
                       &g_q[((size_t)h*SQ + q0 + r) * DH + q*8]);
        }
        CP_COMMIT();
        load_kv(0);
        CP_COMMIT();
        if (qb >= 1) load_kv(1);
        CP_COMMIT();
        CP_WAIT(2);
        __syncthreads();

        uint32_t qa[4][4];
        #pragma unroll
        for (int kc = 0; kc < 4; kc++) {
            int row = mw + ((g & 1) << 3) + l7;
            int byo = kc*32 + ((g >> 1) << 4);
            ldsm_x4(qa[kc][0], qa[kc][1], qa[kc][2], qa[kc][3],
                    sQ + SWZ128((uint32_t)(row*128 + byo)));
        }

        float m0 = -1e30f, m1 = -1e30f, l0 = 0.f, l1 = 0.f;
        float oa[8][4] = {};

        for (int kt = 0; kt <= qb; kt++) {
            const uint32_t kb_off = (uint32_t)((kt % 3) * 8192);
            CP_WAIT(1);
            __syncthreads();
            if (kt + 2 <= qb) load_kv(kt + 2);
            CP_COMMIT();

            float sacc[8][4] = {};
            #pragma unroll
            for (int kc = 0; kc < 4; kc++) {
                uint32_t b[16];
                #pragma unroll
                for (int nb = 0; nb < 4; nb++) {
                    int row = nb*16 + ((g >> 1) << 3) + l7;
                    int byo = kc*32 + ((g & 1) << 4);
                    ldsm_x4(b[nb*4+0], b[nb*4+1], b[nb*4+2], b[nb*4+3],
                            sK + kb_off + SWZ128((uint32_t)(row*128 + byo)));
                }
                #pragma unroll
                for (int ni = 0; ni < 8; ni++)
                    mma_f16(sacc[ni], qa[kc], b[(ni>>1)*4 + (ni&1)*2],
                                              b[(ni>>1)*4 + (ni&1)*2 + 1]);
            }

            const bool diag = (kt == qb);
            if (diag) {
                #pragma unroll
                for (int ni = 0; ni < 8; ni++) {
                    int col = ni*8 + ec;
                    int row0 = mw + r_loc, row1 = row0 + 8;
                    if (col     > row0) sacc[ni][0] = -1e30f;
                    if (col + 1 > row0) sacc[ni][1] = -1e30f;
                    if (col     > row1) sacc[ni][2] = -1e30f;
                    if (col + 1 > row1) sacc[ni][3] = -1e30f;
                }
            }

            float rx0 = -1e30f, rx1 = -1e30f;
            #pragma unroll
            for (int ni = 0; ni < 8; ni++) {
                rx0 = fmaxf(rx0, fmaxf(sacc[ni][0], sacc[ni][1]));
                rx1 = fmaxf(rx1, fmaxf(sacc[ni][2], sacc[ni][3]));
            }
            rx0 = fmaxf(rx0, __shfl_xor_sync(0xffffffffu, rx0, 1));
            rx0 = fmaxf(rx0, __shfl_xor_sync(0xffffffffu, rx0, 2));
            rx1 = fmaxf(rx1, __shfl_xor_sync(0xffffffffu, rx1, 1));
            rx1 = fmaxf(rx1, __shfl_xor_sync(0xffffffffu, rx1, 2));
            float mn0 = fmaxf(m0, rx0), mn1 = fmaxf(m1, rx1);
            float c0 = ex2(m0 - mn0), c1 = ex2(m1 - mn1);

            uint32_t prow0[8], prow1[8];
            #pragma unroll
            for (int ni = 0; ni < 8; ni++) {
                prow0[ni] = h2ex2(packh2(sacc[ni][0] - mn0, sacc[ni][1] - mn0));
                prow1[ni] = h2ex2(packh2(sacc[ni][2] - mn1, sacc[ni][3] - mn1));
            }

            m0 = mn0; m1 = mn1;
            #pragma unroll
            for (int ni = 0; ni < 8; ni++) {
                oa[ni][0] *= c0; oa[ni][1] *= c0;
                oa[ni][2] *= c1; oa[ni][3] *= c1;
            }

            float lacc[4] = {};
            #pragma unroll
            for (int ks = 0; ks < 4; ks++) {
                uint32_t a[4];
                a[0] = prow0[2*ks];
                a[1] = prow1[2*ks];
                a[2] = prow0[2*ks+1];
                a[3] = prow1[2*ks+1];

                mma_f16(lacc, a, H2ONE, H2ONE);

                uint32_t b[16];
                #pragma unroll
                for (int nb = 0; nb < 4; nb++) {
                    int rowb = nb*16 + ((g >> 1) << 3) + l7;
                    int byob = ks*32 + ((g & 1) << 4);
                    ldsm_x4(b[nb*4+0], b[nb*4+1], b[nb*4+2], b[nb*4+3],
                            sV + kb_off + SWZ128((uint32_t)(rowb*128 + byob)));
                }
                #pragma unroll
                for (int ni = 0; ni < 8; ni++)
                    mma_f16(oa[ni], a, b[(ni>>1)*4 + (ni&1)*2],
                                       b[(ni>>1)*4 + (ni&1)*2 + 1]);
            }
            l0 = l0 * c0 + lacc[0];
            l1 = l1 * c1 + lacc[2];
        }

        float inv0 = 1.f / l0, inv1 = 1.f / l1;
        int row0 = q0 + mw + r_loc;
        #pragma unroll
        for (int ni = 0; ni < 8; ni++) {
            int e = ni*8 + ec;
            *(uint32_t*)&g_z[((size_t)h*SQ + row0    ) * DH + e] =
                packh2(oa[ni][0]*inv0, oa[ni][1]*inv0);
            *(uint32_t*)&g_z[((size_t)h*SQ + row0 + 8) * DH + e] =
                packh2(oa[ni][2]*inv1, oa[ni][3]*inv1);
        }
    }
}

// ---------------- Output projection: fp16 HMMA, persistent, d-tile 64 -----------
// dyn smem: Z @0 (16KB), W @16384 (3x8KB) = 40KB; 2 CTAs/SM
__global__ __launch_bounds__(256, 2) void outproj_mma_kernel(
    const float* __restrict__ bO, float* __restrict__ out)
{
    extern __shared__ uint8_t dsm[];
    const uint32_t sZ = smem_u32(dsm);
    const uint32_t sW = sZ + 16384;

    const int tid = threadIdx.x, w = tid >> 5, lane = tid & 31;
    const int s0 = blockIdx.x * 128, h = blockIdx.y;
    const __half* WOT = g_wot + (size_t)h * DM * DH;

    const int mw = w * 16;
    const int g  = lane >> 3, l7 = lane & 7;

    auto prefetch_w = [&](int d) {
        const int d0 = d * 64;
        const uint32_t base = sW + (uint32_t)((d % 3) * 8192);
        #pragma unroll
        for (int i = 0; i < 2; i++) {
            int idx = tid + i * 256, r = idx >> 3, q = idx & 7;
            CP_ASYNC16(base + SWZ128((uint32_t)(r*128 + q*16)),
                       &WOT[(size_t)(d0 + r) * DH + q*8]);
        }
    };

    // Z tile 128 x 64 fp16 = 16KB
    #pragma unroll
    for (int i = 0; i < 4; i++) {
        int idx = tid + i * 256, r = idx >> 3, q = idx & 7;
        CP_ASYNC16(sZ + SWZ128((uint32_t)(r*128 + q*16)),
                   &g_z[((size_t)h*SQ + s0 + r) * DH + q*8]);
    }
    prefetch_w(0);
    CP_COMMIT();
    prefetch_w(1);
    CP_COMMIT();

    const int r0 = mw + (lane >> 2);
    const int ec = (lane & 3) * 2;

    // A fragments (Z) are d-tile invariant: load once after first wait
    uint32_t za[4][4];
    bool za_loaded = false;

    #pragma unroll 1
    for (int d = 0; d < 16; d++) {
        CP_WAIT(1);
        __syncthreads();
        if (d + 2 < 16) prefetch_w(d + 2);
        CP_COMMIT();

        if (!za_loaded) {
            #pragma unroll
            for (int kc = 0; kc < 4; kc++) {
                int row = mw + ((g & 1) << 3) + l7;
                int byo = kc*32 + ((g >> 1) << 4);
                ldsm_x4(za[kc][0], za[kc][1], za[kc][2], za[kc][3],
                        sZ + SWZ128((uint32_t)(row*128 + byo)));
            }
            za_loaded = true;
        }

        const uint32_t sbW = sW + (uint32_t)((d % 3) * 8192);
        float acc[8][4] = {};

        #pragma unroll
        for (int kc = 0; kc < 4; kc++) {
            uint32_t b[16];
            #pragma unroll
            for (int nb = 0; nb < 4; nb++) {
                int row = nb * 16 + ((g >> 1) << 3) + l7;
                int byo = kc*32 + ((g & 1) << 4);
                ldsm_x4(b[nb*4+0], b[nb*4+1], b[nb*4+2], b[nb*4+3],
                        sbW + SWZ128((uint32_t)(row*128 + byo)));
            }
            #pragma unroll
            for (int ni = 0; ni < 8; ni++)
                mma_f16(acc[ni], za[kc], b[(ni >> 1)*4 + (ni & 1)*2],
                                         b[(ni >> 1)*4 + (ni & 1)*2 + 1]);
        }

        const int d0 = d * 64;
        #pragma unroll
        for (int ni = 0; ni < 8; ni++) {
            int dg = d0 + ni*8 + ec;
            float b0 = bO[dg] * 0.0625f, b1 = bO[dg + 1] * 0.0625f;
            int sg0 = s0 + r0, sg1 = sg0 + 8;
            *(float2*)&out[((size_t)sg0 * NH + h) * DM + dg] =
                make_float2(acc[ni][0] + b0, acc[ni][1] + b1);
            *(float2*)&out[((size_t)sg1 * NH + h) * DM + dg] =
                make_float2(acc[ni][2] + b0, acc[ni][3] + b1);
        }
    }
}

// -------------------------------------------------------------------------------
extern "C" void kernel_launch(void* const* d_in, const int* in_sizes, int n_in,
                              void* d_out, int out_size)
{
    (void)in_sizes; (void)n_in; (void)out_size;
    const float* xq = (const float*)d_in[0];
    const float* xk = (const float*)d_in[1];
    const float* xv = (const float*)d_in[2];
    const float* WQ = (const float*)d_in[3];
    const float* bQ = (const float*)d_in[4];
    const float* WK = (const float*)d_in[5];
    const float* bK = (const float*)d_in[6];
    const float* WV = (const float*)d_in[7];
    const float* bV = (const float*)d_in[8];
    const float* WO = (const float*)d_in[9];
    const float* bO = (const float*)d_in[10];
    float* out = (float*)d_out;

    static int smem_set = 0;
    if (!smem_set) {
        cudaFuncSetAttribute(attn_mma_kernel,
                             cudaFuncAttributeMaxDynamicSharedMemorySize, 57344);
        cudaFuncSetAttribute(proj_mma_kernel,
                             cudaFuncAttributeMaxDynamicSharedMemorySize, 98304);
        cudaFuncSetAttribute(outproj_mma_kernel,
                             cudaFuncAttributeMaxDynamicSharedMemorySize, 40960);
        smem_set = 1;
    }

    rope_tab_kernel<<<256, 256>>>();
    transpose_w_kernel<<<dim3(64, 64), dim3(32, 8)>>>(WQ, WK, WV, WO);
    proj_mma_kernel<<<dim3(16, 16, 3), 256, 98304>>>(xq, xk, xv, bQ, bK, bV);
    attn_mma_kernel<<<dim3(16, 16), 128, 57344>>>();
    outproj_mma_kernel<<<dim3(16, 16), 256, 40960>>>(bO, out);
}